// round 1
// baseline (speedup 1.0000x reference)
#include <cuda_runtime.h>

#define HID    1024
#define SEQ    1024
#define BATCH  4
#define NHEADS 16
#define DH     64
#define MROWS  (SEQ * BATCH)      // 4096
#define BHTOT  (BATCH * NHEADS)   // 64

// Scratch for Q/K/V in (B,H,S,Dh) layout. 3 x 16.78 MB, static device arrays
// (no allocation -> allocation-guard safe).
__device__ float g_q[BHTOT * SEQ * DH];
__device__ float g_k[BHTOT * SEQ * DH];
__device__ float g_v[BHTOT * SEQ * DH];

// ---------------------------------------------------------------------------
// Fused QKV projection: out = X @ W^T + b, with output scattered into
// (B,H,S,Dh) layout. X is (S,B,HID) row-major => row m = s*BATCH+b.
// grid = (N/64, M/64, 3), block = 256 (16x16), 4x4 microtile, K-chunk 32.
// ---------------------------------------------------------------------------
__global__ __launch_bounds__(256) void qkv_gemm_kernel(
    const float* __restrict__ X,
    const float* __restrict__ W0, const float* __restrict__ b0,
    const float* __restrict__ W1, const float* __restrict__ b1,
    const float* __restrict__ W2, const float* __restrict__ b2)
{
    __shared__ float As[32][68];   // [k][m], padded
    __shared__ float Ws[32][68];   // [k][n], padded

    const int tid = threadIdx.x;
    const int tx  = tid & 15;      // -> 4 output cols
    const int ty  = tid >> 4;      // -> 4 output rows
    const int m0  = blockIdx.y * 64;
    const int n0  = blockIdx.x * 64;
    const int z   = blockIdx.z;

    const float* W    = (z == 0) ? W0 : (z == 1) ? W1 : W2;
    const float* bias = (z == 0) ? b0 : (z == 1) ? b1 : b2;
    float*       out  = (z == 0) ? g_q : (z == 1) ? g_k : g_v;

    float acc[4][4];
    #pragma unroll
    for (int i = 0; i < 4; i++)
        #pragma unroll
        for (int j = 0; j < 4; j++) acc[i][j] = 0.f;

    for (int k0 = 0; k0 < HID; k0 += 32) {
        #pragma unroll
        for (int i = tid; i < 64 * 32; i += 256) {
            int r = i >> 5, c = i & 31;
            As[c][r] = X[(m0 + r) * HID + k0 + c];
            Ws[c][r] = W[(n0 + r) * HID + k0 + c];
        }
        __syncthreads();

        #pragma unroll
        for (int kk = 0; kk < 32; kk++) {
            float4 a4 = *(const float4*)&As[kk][ty * 4];
            float4 w4 = *(const float4*)&Ws[kk][tx * 4];
            float a[4] = {a4.x, a4.y, a4.z, a4.w};
            float w[4] = {w4.x, w4.y, w4.z, w4.w};
            #pragma unroll
            for (int i = 0; i < 4; i++)
                #pragma unroll
                for (int j = 0; j < 4; j++)
                    acc[i][j] = fmaf(a[i], w[j], acc[i][j]);
        }
        __syncthreads();
    }

    // Scatter into (B,H,S,Dh)
    #pragma unroll
    for (int i = 0; i < 4; i++) {
        int m = m0 + ty * 4 + i;
        int s = m >> 2;           // row m = s*4 + b
        int b = m & 3;
        #pragma unroll
        for (int j = 0; j < 4; j++) {
            int n = n0 + tx * 4 + j;
            int h = n >> 6;       // n = h*64 + d
            int d = n & 63;
            out[((b * NHEADS + h) * SEQ + s) * DH + d] = acc[i][j] + bias[n];
        }
    }
}

// ---------------------------------------------------------------------------
// Flash-style attention. grid = (SEQ/64, B*H), block = 256 (16x16).
// Each block: 64 queries x full key sweep in 64-key tiles, online softmax.
// Dynamic smem: Qs, Ks, Vs, Ps each 64 x 68 floats.
// ---------------------------------------------------------------------------
#define ATTN_SMEM (4 * 64 * 68 * (int)sizeof(float))

__global__ __launch_bounds__(256) void attn_kernel(
    const float* __restrict__ mask, float* __restrict__ out)
{
    extern __shared__ float sm[];
    float* Qs = sm;                 // [64][68]
    float* Ks = Qs + 64 * 68;
    float* Vs = Ks + 64 * 68;
    float* Ps = Vs + 64 * 68;

    const int tid = threadIdx.x;
    const int tx  = tid & 15;       // 4 key-cols / 4 out-dims
    const int ty  = tid >> 4;       // 4 query rows
    const int bh  = blockIdx.y;
    const int b   = bh >> 4;
    const int h   = bh & 15;
    const int q0  = blockIdx.x * 64;

    // Load Q tile (64x64)
    const float* qg = g_q + (size_t)(bh * SEQ + q0) * DH;
    #pragma unroll
    for (int i = tid; i < 64 * 16; i += 256) {
        int r = i >> 4, c4 = (i & 15) * 4;
        *(float4*)&Qs[r * 68 + c4] = *(const float4*)&qg[r * 64 + c4];
    }

    float m_run[4], l_run[4], acc[4][4];
    #pragma unroll
    for (int i = 0; i < 4; i++) {
        m_run[i] = -1e30f;
        l_run[i] = 0.f;
        #pragma unroll
        for (int j = 0; j < 4; j++) acc[i][j] = 0.f;
    }

    const float scale = 0.125f;     // 1/sqrt(64)
    const float* mbase = mask + (size_t)b * SEQ * SEQ;

    for (int k0 = 0; k0 < SEQ; k0 += 64) {
        __syncthreads();            // protect Ks/Vs/Ps reuse (and Q load, iter 0)
        const float* kg = g_k + (size_t)(bh * SEQ + k0) * DH;
        const float* vg = g_v + (size_t)(bh * SEQ + k0) * DH;
        #pragma unroll
        for (int i = tid; i < 64 * 16; i += 256) {
            int r = i >> 4, c4 = (i & 15) * 4;
            *(float4*)&Ks[r * 68 + c4] = *(const float4*)&kg[r * 64 + c4];
            *(float4*)&Vs[r * 68 + c4] = *(const float4*)&vg[r * 64 + c4];
        }
        __syncthreads();

        // S = Q K^T  (4x4 per thread)
        float s[4][4];
        #pragma unroll
        for (int i = 0; i < 4; i++)
            #pragma unroll
            for (int j = 0; j < 4; j++) s[i][j] = 0.f;

        #pragma unroll
        for (int d = 0; d < 64; d += 4) {
            float4 q4[4], k4[4];
            #pragma unroll
            for (int i = 0; i < 4; i++)
                q4[i] = *(const float4*)&Qs[(ty * 4 + i) * 68 + d];
            #pragma unroll
            for (int j = 0; j < 4; j++)
                k4[j] = *(const float4*)&Ks[(tx * 4 + j) * 68 + d];
            #pragma unroll
            for (int i = 0; i < 4; i++)
                #pragma unroll
                for (int j = 0; j < 4; j++) {
                    s[i][j] = fmaf(q4[i].x, k4[j].x, s[i][j]);
                    s[i][j] = fmaf(q4[i].y, k4[j].y, s[i][j]);
                    s[i][j] = fmaf(q4[i].z, k4[j].z, s[i][j]);
                    s[i][j] = fmaf(q4[i].w, k4[j].w, s[i][j]);
                }
        }

        // mask + scale, online softmax update
        float p[4][4];
        #pragma unroll
        for (int i = 0; i < 4; i++) {
            float4 mv = *(const float4*)&mbase[(size_t)(q0 + ty * 4 + i) * SEQ + k0 + tx * 4];
            s[i][0] = fmaf(s[i][0], scale, mv.x);
            s[i][1] = fmaf(s[i][1], scale, mv.y);
            s[i][2] = fmaf(s[i][2], scale, mv.z);
            s[i][3] = fmaf(s[i][3], scale, mv.w);

            float tm = fmaxf(fmaxf(s[i][0], s[i][1]), fmaxf(s[i][2], s[i][3]));
            #pragma unroll
            for (int off = 1; off < 16; off <<= 1)
                tm = fmaxf(tm, __shfl_xor_sync(0xffffffffu, tm, off));

            float m_new = fmaxf(m_run[i], tm);
            float c     = __expf(m_run[i] - m_new);

            float rs = 0.f;
            #pragma unroll
            for (int j = 0; j < 4; j++) {
                p[i][j] = __expf(s[i][j] - m_new);
                rs += p[i][j];
            }
            #pragma unroll
            for (int off = 1; off < 16; off <<= 1)
                rs += __shfl_xor_sync(0xffffffffu, rs, off);

            l_run[i] = l_run[i] * c + rs;
            m_run[i] = m_new;
            #pragma unroll
            for (int j = 0; j < 4; j++) acc[i][j] *= c;
        }

        // Stage P for the PV product
        #pragma unroll
        for (int i = 0; i < 4; i++)
            #pragma unroll
            for (int j = 0; j < 4; j++)
                Ps[(ty * 4 + i) * 68 + tx * 4 + j] = p[i][j];
        __syncthreads();

        // acc += P V
        #pragma unroll
        for (int k = 0; k < 64; k += 4) {
            float4 p4[4], v4[4];
            #pragma unroll
            for (int i = 0; i < 4; i++)
                p4[i] = *(const float4*)&Ps[(ty * 4 + i) * 68 + k];
            #pragma unroll
            for (int kk = 0; kk < 4; kk++)
                v4[kk] = *(const float4*)&Vs[(k + kk) * 68 + tx * 4];
            #pragma unroll
            for (int i = 0; i < 4; i++) {
                acc[i][0] = fmaf(p4[i].x, v4[0].x, acc[i][0]);
                acc[i][1] = fmaf(p4[i].x, v4[0].y, acc[i][1]);
                acc[i][2] = fmaf(p4[i].x, v4[0].z, acc[i][2]);
                acc[i][3] = fmaf(p4[i].x, v4[0].w, acc[i][3]);
                acc[i][0] = fmaf(p4[i].y, v4[1].x, acc[i][0]);
                acc[i][1] = fmaf(p4[i].y, v4[1].y, acc[i][1]);
                acc[i][2] = fmaf(p4[i].y, v4[1].z, acc[i][2]);
                acc[i][3] = fmaf(p4[i].y, v4[1].w, acc[i][3]);
                acc[i][0] = fmaf(p4[i].z, v4[2].x, acc[i][0]);
                acc[i][1] = fmaf(p4[i].z, v4[2].y, acc[i][1]);
                acc[i][2] = fmaf(p4[i].z, v4[2].z, acc[i][2]);
                acc[i][3] = fmaf(p4[i].z, v4[2].w, acc[i][3]);
                acc[i][0] = fmaf(p4[i].w, v4[3].x, acc[i][0]);
                acc[i][1] = fmaf(p4[i].w, v4[3].y, acc[i][1]);
                acc[i][2] = fmaf(p4[i].w, v4[3].z, acc[i][2]);
                acc[i][3] = fmaf(p4[i].w, v4[3].w, acc[i][3]);
            }
        }
    }

    // Epilogue: normalize and write (S,B,HID)
    #pragma unroll
    for (int i = 0; i < 4; i++) {
        int q = q0 + ty * 4 + i;
        float inv = 1.0f / l_run[i];
        float4 o;
        o.x = acc[i][0] * inv;
        o.y = acc[i][1] * inv;
        o.z = acc[i][2] * inv;
        o.w = acc[i][3] * inv;
        *(float4*)&out[(size_t)q * BATCH * HID + b * HID + h * DH + tx * 4] = o;
    }
}

// ---------------------------------------------------------------------------
// Launch
// ---------------------------------------------------------------------------
extern "C" void kernel_launch(void* const* d_in, const int* in_sizes, int n_in,
                              void* d_out, int out_size)
{
    const float* X    = (const float*)d_in[0];
    const float* mask = (const float*)d_in[1];
    const float* Wq   = (const float*)d_in[2];
    const float* bq   = (const float*)d_in[3];
    const float* Wk   = (const float*)d_in[4];
    const float* bk   = (const float*)d_in[5];
    const float* Wv   = (const float*)d_in[6];
    const float* bv   = (const float*)d_in[7];
    float* out = (float*)d_out;

    dim3 ggrid(HID / 64, MROWS / 64, 3);
    qkv_gemm_kernel<<<ggrid, 256>>>(X, Wq, bq, Wk, bk, Wv, bv);

    cudaFuncSetAttribute(attn_kernel,
                         cudaFuncAttributeMaxDynamicSharedMemorySize, ATTN_SMEM);
    dim3 agrid(SEQ / 64, BHTOT);
    attn_kernel<<<agrid, 256, ATTN_SMEM>>>(mask, out);
}

// round 4
// speedup vs baseline: 2.2143x; 2.2143x over previous
#include <cuda_runtime.h>
#include <cuda_bf16.h>
#include <cstdint>

#define HID    1024
#define SEQ    1024
#define BATCH  4
#define NHEADS 16
#define DH     64
#define MROWS  (SEQ * BATCH)      // 4096
#define BHTOT  (BATCH * NHEADS)   // 64

// ---------------------------------------------------------------------------
// Device scratch (static -> allocation-guard safe)
// Q/K/V row-major (m, n): m = s*BATCH + b, n = h*64 + d
// ---------------------------------------------------------------------------
__device__ __align__(16) float g_q[MROWS * HID];
__device__ __align__(16) float g_k[MROWS * HID];
__device__ __align__(16) float g_v[MROWS * HID];
__device__ __align__(16) __nv_bfloat16 g_xhi[MROWS * HID];
__device__ __align__(16) __nv_bfloat16 g_xlo[MROWS * HID];
__device__ __align__(16) __nv_bfloat16 g_whi[3 * HID * HID];
__device__ __align__(16) __nv_bfloat16 g_wlo[3 * HID * HID];

// ---------------------------------------------------------------------------
// mma.sync m16n8k16 bf16 (row.col), fp32 accumulate
// ---------------------------------------------------------------------------
__device__ __forceinline__ void mma16816(float* d, const uint32_t* a,
                                         const uint32_t* b) {
    asm volatile(
        "mma.sync.aligned.m16n8k16.row.col.f32.bf16.bf16.f32 "
        "{%0,%1,%2,%3}, {%4,%5,%6,%7}, {%8,%9}, {%0,%1,%2,%3};"
        : "+f"(d[0]), "+f"(d[1]), "+f"(d[2]), "+f"(d[3])
        : "r"(a[0]), "r"(a[1]), "r"(a[2]), "r"(a[3]),
          "r"(b[0]), "r"(b[1]));
}

// ---------------------------------------------------------------------------
// Split fp32 -> (hi, lo) bf16 pair.  which: 0=X, 1=Wq, 2=Wk, 3=Wv
// ---------------------------------------------------------------------------
__global__ void split_kernel(const float4* __restrict__ src, int which, int n4)
{
    __nv_bfloat16* hi;
    __nv_bfloat16* lo;
    if (which == 0) { hi = g_xhi; lo = g_xlo; }
    else { hi = g_whi + (size_t)(which - 1) * HID * HID;
           lo = g_wlo + (size_t)(which - 1) * HID * HID; }

    int i = blockIdx.x * blockDim.x + threadIdx.x;
    int stride = gridDim.x * blockDim.x;
    for (; i < n4; i += stride) {
        float4 v = src[i];
        __nv_bfloat16 h0 = __float2bfloat16(v.x);
        __nv_bfloat16 h1 = __float2bfloat16(v.y);
        __nv_bfloat16 h2 = __float2bfloat16(v.z);
        __nv_bfloat16 h3 = __float2bfloat16(v.w);
        __nv_bfloat16 l0 = __float2bfloat16(v.x - __bfloat162float(h0));
        __nv_bfloat16 l1 = __float2bfloat16(v.y - __bfloat162float(h1));
        __nv_bfloat16 l2 = __float2bfloat16(v.z - __bfloat162float(h2));
        __nv_bfloat16 l3 = __float2bfloat16(v.w - __bfloat162float(h3));
        __nv_bfloat162 hp0(h0, h1), hp1(h2, h3), lp0(l0, l1), lp1(l2, l3);
        uint2 hv, lv;
        hv.x = *(uint32_t*)&hp0; hv.y = *(uint32_t*)&hp1;
        lv.x = *(uint32_t*)&lp0; lv.y = *(uint32_t*)&lp1;
        ((uint2*)hi)[i] = hv;
        ((uint2*)lo)[i] = lv;
    }
}

// ---------------------------------------------------------------------------
// Split-bf16 GEMM via mma.sync:  C[m][n] = X[m][:] . W[n][:] + bias[n]
// CTA tile 128x128, 8 warps -> warp tile 32(M) x 64(N), K-chunk 64.
// smem row stride 72 halves (36 words): frag LDS banks = 4g+c, conflict-free.
// grid = (HID/128, MROWS/128, 3), block = 256.
// ---------------------------------------------------------------------------
#define TROW   72                      // halves per smem row (64 data + 8 pad)
#define TWORDS (128 * (TROW / 2))      // 4608 words per tile
#define GEMM_SMEM (4 * 128 * TROW * 2) // 73728 bytes

__global__ __launch_bounds__(256) void gemm_kernel(
    const float* __restrict__ b0,
    const float* __restrict__ b1,
    const float* __restrict__ b2)
{
    extern __shared__ __align__(16) __nv_bfloat16 sm[];
    __nv_bfloat16* tAhi = sm;
    __nv_bfloat16* tAlo = sm + 128 * TROW;
    __nv_bfloat16* tBhi = sm + 2 * 128 * TROW;
    __nv_bfloat16* tBlo = sm + 3 * 128 * TROW;
    const uint32_t* smw = (const uint32_t*)sm;

    const int tid  = threadIdx.x;
    const int wid  = tid >> 5;
    const int lane = tid & 31;
    const int g    = lane >> 2;       // fragment row group 0..7
    const int cq   = lane & 3;        // fragment col group 0..3

    const int n0 = blockIdx.x * 128;
    const int m0 = blockIdx.y * 128;
    const int z  = blockIdx.z;

    const __nv_bfloat16* Wh = g_whi + (size_t)z * HID * HID;
    const __nv_bfloat16* Wl = g_wlo + (size_t)z * HID * HID;
    const float* bias = (z == 0) ? b0 : (z == 1) ? b1 : b2;
    float*       out  = (z == 0) ? g_q : (z == 1) ? g_k : g_v;

    const int wm = (wid & 3) * 32;    // warp M offset in CTA tile
    const int wn = (wid >> 2) * 64;   // warp N offset

    float acc[2][8][4];
    #pragma unroll
    for (int mi = 0; mi < 2; mi++)
        #pragma unroll
        for (int nj = 0; nj < 8; nj++)
            #pragma unroll
            for (int r = 0; r < 4; r++) acc[mi][nj][r] = 0.f;

    const int lrow = tid >> 3;            // 0..31 (row within pass)
    const int lcol = (tid & 7) * 8;       // half offset within row (16B grain)

    for (int c = 0; c < HID / 64; c++) {
        const int k0 = c * 64;
        #pragma unroll
        for (int rr = 0; rr < 128; rr += 32) {
            const int row = rr + lrow;
            *(float4*)&tAhi[row * TROW + lcol] =
                *(const float4*)&g_xhi[(size_t)(m0 + row) * HID + k0 + lcol];
            *(float4*)&tAlo[row * TROW + lcol] =
                *(const float4*)&g_xlo[(size_t)(m0 + row) * HID + k0 + lcol];
            *(float4*)&tBhi[row * TROW + lcol] =
                *(const float4*)&Wh[(size_t)(n0 + row) * HID + k0 + lcol];
            *(float4*)&tBlo[row * TROW + lcol] =
                *(const float4*)&Wl[(size_t)(n0 + row) * HID + k0 + lcol];
        }
        __syncthreads();

        #pragma unroll
        for (int ks = 0; ks < 4; ks++) {
            // A fragments (hi & lo) for both 16-row tiles
            uint32_t ah[2][4], al[2][4];
            #pragma unroll
            for (int mi = 0; mi < 2; mi++) {
                const int base = (wm + mi * 16 + g) * (TROW / 2) + ks * 8 + cq;
                ah[mi][0] = smw[base];
                ah[mi][1] = smw[base + 8 * (TROW / 2)];
                ah[mi][2] = smw[base + 4];
                ah[mi][3] = smw[base + 8 * (TROW / 2) + 4];
                al[mi][0] = smw[TWORDS + base];
                al[mi][1] = smw[TWORDS + base + 8 * (TROW / 2)];
                al[mi][2] = smw[TWORDS + base + 4];
                al[mi][3] = smw[TWORDS + base + 8 * (TROW / 2) + 4];
            }
            #pragma unroll
            for (int nj = 0; nj < 8; nj++) {
                const int bbase = (wn + nj * 8 + g) * (TROW / 2) + ks * 8 + cq;
                uint32_t bh[2], bl[2];
                bh[0] = smw[2 * TWORDS + bbase];
                bh[1] = smw[2 * TWORDS + bbase + 4];
                bl[0] = smw[3 * TWORDS + bbase];
                bl[1] = smw[3 * TWORDS + bbase + 4];
                #pragma unroll
                for (int mi = 0; mi < 2; mi++) {
                    mma16816(acc[mi][nj], ah[mi], bh);   // hi*hi
                    mma16816(acc[mi][nj], ah[mi], bl);   // hi*lo
                    mma16816(acc[mi][nj], al[mi], bh);   // lo*hi
                }
            }
        }
        __syncthreads();
    }

    // Epilogue: C + bias -> out
    #pragma unroll
    for (int mi = 0; mi < 2; mi++) {
        const int r0 = m0 + wm + mi * 16 + g;
        #pragma unroll
        for (int nj = 0; nj < 8; nj++) {
            const int col = n0 + wn + nj * 8 + cq * 2;
            const float bz0 = __ldg(&bias[col]);
            const float bz1 = __ldg(&bias[col + 1]);
            float2 v0, v1;
            v0.x = acc[mi][nj][0] + bz0;
            v0.y = acc[mi][nj][1] + bz1;
            v1.x = acc[mi][nj][2] + bz0;
            v1.y = acc[mi][nj][3] + bz1;
            *(float2*)&out[(size_t)r0 * HID + col] = v0;
            *(float2*)&out[(size_t)(r0 + 8) * HID + col] = v1;
        }
    }
}

// ---------------------------------------------------------------------------
// Flash-style attention. grid = (SEQ/64, B*H), block = 256 (16x16).
// Key-column mapping per thread is STRIDED (col = tx + 16*j) so the K-fragment
// LDS.128 banks are (4*tx + d) mod 32 -> conflict-free (was 8-way at tx*4+j).
// ---------------------------------------------------------------------------
#define ATTN_SMEM (4 * 64 * 68 * (int)sizeof(float))

__global__ __launch_bounds__(256) void attn_kernel(
    const float* __restrict__ mask, float* __restrict__ out)
{
    extern __shared__ float smf[];
    float* Qs = smf;                // [64][68]
    float* Ks = Qs + 64 * 68;
    float* Vs = Ks + 64 * 68;
    float* Ps = Vs + 64 * 68;

    const int tid = threadIdx.x;
    const int tx  = tid & 15;
    const int ty  = tid >> 4;
    const int bh  = blockIdx.y;
    const int b   = bh >> 4;
    const int h   = bh & 15;
    const int q0  = blockIdx.x * 64;

    // Q tile: row r -> global row (q0+r)*BATCH + b, cols h*64..h*64+63
    const float* qg = g_q + ((size_t)q0 * BATCH + b) * HID + h * DH;
    #pragma unroll
    for (int i = tid; i < 64 * 16; i += 256) {
        int r = i >> 4, c4 = (i & 15) * 4;
        *(float4*)&Qs[r * 68 + c4] = *(const float4*)&qg[(size_t)r * (BATCH * HID) + c4];
    }

    float m_run[4], l_run[4], acc[4][4];
    #pragma unroll
    for (int i = 0; i < 4; i++) {
        m_run[i] = -1e30f;
        l_run[i] = 0.f;
        #pragma unroll
        for (int j = 0; j < 4; j++) acc[i][j] = 0.f;
    }

    const float scale = 0.125f;
    const float* mbase = mask + (size_t)b * SEQ * SEQ;

    for (int k0 = 0; k0 < SEQ; k0 += 64) {
        __syncthreads();
        const float* kg = g_k + ((size_t)k0 * BATCH + b) * HID + h * DH;
        const float* vg = g_v + ((size_t)k0 * BATCH + b) * HID + h * DH;
        #pragma unroll
        for (int i = tid; i < 64 * 16; i += 256) {
            int r = i >> 4, c4 = (i & 15) * 4;
            *(float4*)&Ks[r * 68 + c4] = *(const float4*)&kg[(size_t)r * (BATCH * HID) + c4];
            *(float4*)&Vs[r * 68 + c4] = *(const float4*)&vg[(size_t)r * (BATCH * HID) + c4];
        }
        __syncthreads();

        // S = Q K^T; this thread's key columns are tx + 16*j
        float s[4][4];
        #pragma unroll
        for (int i = 0; i < 4; i++)
            #pragma unroll
            for (int j = 0; j < 4; j++) s[i][j] = 0.f;

        #pragma unroll
        for (int d = 0; d < 64; d += 4) {
            float4 q4[4], k4[4];
            #pragma unroll
            for (int i = 0; i < 4; i++)
                q4[i] = *(const float4*)&Qs[(ty * 4 + i) * 68 + d];
            #pragma unroll
            for (int j = 0; j < 4; j++)
                k4[j] = *(const float4*)&Ks[(tx + 16 * j) * 68 + d];
            #pragma unroll
            for (int i = 0; i < 4; i++)
                #pragma unroll
                for (int j = 0; j < 4; j++) {
                    s[i][j] = fmaf(q4[i].x, k4[j].x, s[i][j]);
                    s[i][j] = fmaf(q4[i].y, k4[j].y, s[i][j]);
                    s[i][j] = fmaf(q4[i].z, k4[j].z, s[i][j]);
                    s[i][j] = fmaf(q4[i].w, k4[j].w, s[i][j]);
                }
        }

        // mask + scale, online softmax
        float p[4][4];
        #pragma unroll
        for (int i = 0; i < 4; i++) {
            const float* mrow = &mbase[(size_t)(q0 + ty * 4 + i) * SEQ + k0];
            #pragma unroll
            for (int j = 0; j < 4; j++)
                s[i][j] = fmaf(s[i][j], scale, __ldg(&mrow[tx + 16 * j]));

            float tm = fmaxf(fmaxf(s[i][0], s[i][1]), fmaxf(s[i][2], s[i][3]));
            #pragma unroll
            for (int off = 1; off < 16; off <<= 1)
                tm = fmaxf(tm, __shfl_xor_sync(0xffffffffu, tm, off));

            float m_new = fmaxf(m_run[i], tm);
            float cc    = __expf(m_run[i] - m_new);

            float rs = 0.f;
            #pragma unroll
            for (int j = 0; j < 4; j++) {
                p[i][j] = __expf(s[i][j] - m_new);
                rs += p[i][j];
            }
            #pragma unroll
            for (int off = 1; off < 16; off <<= 1)
                rs += __shfl_xor_sync(0xffffffffu, rs, off);

            l_run[i] = l_run[i] * cc + rs;
            m_run[i] = m_new;
            #pragma unroll
            for (int j = 0; j < 4; j++) acc[i][j] *= cc;
        }

        // Stage P (column c stores prob of key k0+c)
        #pragma unroll
        for (int i = 0; i < 4; i++)
            #pragma unroll
            for (int j = 0; j < 4; j++)
                Ps[(ty * 4 + i) * 68 + tx + 16 * j] = p[i][j];
        __syncthreads();

        // acc += P V
        #pragma unroll
        for (int k = 0; k < 64; k += 4) {
            float4 p4[4], v4[4];
            #pragma unroll
            for (int i = 0; i < 4; i++)
                p4[i] = *(const float4*)&Ps[(ty * 4 + i) * 68 + k];
            #pragma unroll
            for (int kk = 0; kk < 4; kk++)
                v4[kk] = *(const float4*)&Vs[(k + kk) * 68 + tx * 4];
            #pragma unroll
            for (int i = 0; i < 4; i++) {
                acc[i][0] = fmaf(p4[i].x, v4[0].x, acc[i][0]);
                acc[i][1] = fmaf(p4[i].x, v4[0].y, acc[i][1]);
                acc[i][2] = fmaf(p4[i].x, v4[0].z, acc[i][2]);
                acc[i][3] = fmaf(p4[i].x, v4[0].w, acc[i][3]);
                acc[i][0] = fmaf(p4[i].y, v4[1].x, acc[i][0]);
                acc[i][1] = fmaf(p4[i].y, v4[1].y, acc[i][1]);
                acc[i][2] = fmaf(p4[i].y, v4[1].z, acc[i][2]);
                acc[i][3] = fmaf(p4[i].y, v4[1].w, acc[i][3]);
                acc[i][0] = fmaf(p4[i].z, v4[2].x, acc[i][0]);
                acc[i][1] = fmaf(p4[i].z, v4[2].y, acc[i][1]);
                acc[i][2] = fmaf(p4[i].z, v4[2].z, acc[i][2]);
                acc[i][3] = fmaf(p4[i].z, v4[2].w, acc[i][3]);
                acc[i][0] = fmaf(p4[i].w, v4[3].x, acc[i][0]);
                acc[i][1] = fmaf(p4[i].w, v4[3].y, acc[i][1]);
                acc[i][2] = fmaf(p4[i].w, v4[3].z, acc[i][2]);
                acc[i][3] = fmaf(p4[i].w, v4[3].w, acc[i][3]);
            }
        }
    }

    // Epilogue: normalize and write (S,B,HID)
    #pragma unroll
    for (int i = 0; i < 4; i++) {
        int q = q0 + ty * 4 + i;
        float inv = 1.0f / l_run[i];
        float4 o;
        o.x = acc[i][0] * inv;
        o.y = acc[i][1] * inv;
        o.z = acc[i][2] * inv;
        o.w = acc[i][3] * inv;
        *(float4*)&out[(size_t)q * BATCH * HID + b * HID + h * DH + tx * 4] = o;
    }
}

// ---------------------------------------------------------------------------
// Launch
// ---------------------------------------------------------------------------
extern "C" void kernel_launch(void* const* d_in, const int* in_sizes, int n_in,
                              void* d_out, int out_size)
{
    const float* X    = (const float*)d_in[0];
    const float* mask = (const float*)d_in[1];
    const float* Wq   = (const float*)d_in[2];
    const float* bq   = (const float*)d_in[3];
    const float* Wk   = (const float*)d_in[4];
    const float* bk   = (const float*)d_in[5];
    const float* Wv   = (const float*)d_in[6];
    const float* bv   = (const float*)d_in[7];
    float* out = (float*)d_out;

    // 1. fp32 -> split bf16
    split_kernel<<<1024, 256>>>((const float4*)X, 0, MROWS * HID / 4);
    split_kernel<<<512, 256>>>((const float4*)Wq, 1, HID * HID / 4);
    split_kernel<<<512, 256>>>((const float4*)Wk, 2, HID * HID / 4);
    split_kernel<<<512, 256>>>((const float4*)Wv, 3, HID * HID / 4);

    // 2. QKV projections on tensor cores (mma.sync, split-bf16)
    cudaFuncSetAttribute(gemm_kernel,
                         cudaFuncAttributeMaxDynamicSharedMemorySize, GEMM_SMEM);
    dim3 ggrid(HID / 128, MROWS / 128, 3);
    gemm_kernel<<<ggrid, 256, GEMM_SMEM>>>(bq, bk, bv);

    // 3. attention
    cudaFuncSetAttribute(attn_kernel,
                         cudaFuncAttributeMaxDynamicSharedMemorySize, ATTN_SMEM);
    dim3 agrid(SEQ / 64, BHTOT);
    attn_kernel<<<agrid, 256, ATTN_SMEM>>>(mask, out);
}

// round 5
// speedup vs baseline: 2.9416x; 1.3285x over previous
#include <cuda_runtime.h>
#include <cuda_bf16.h>
#include <cstdint>

#define HID    1024
#define SEQ    1024
#define BATCH  4
#define NHEADS 16
#define DH     64
#define MROWS  (SEQ * BATCH)      // 4096
#define BHTOT  (BATCH * NHEADS)   // 64

// ---------------------------------------------------------------------------
// Device scratch (static -> allocation-guard safe)
// Q/K/V stored as bf16 hi/lo pairs, row-major (m, n): m = s*BATCH+b, n = h*64+d
// ---------------------------------------------------------------------------
__device__ __align__(16) __nv_bfloat16 g_qhi[MROWS * HID];
__device__ __align__(16) __nv_bfloat16 g_qlo[MROWS * HID];
__device__ __align__(16) __nv_bfloat16 g_khi[MROWS * HID];
__device__ __align__(16) __nv_bfloat16 g_klo[MROWS * HID];
__device__ __align__(16) __nv_bfloat16 g_vhi[MROWS * HID];
__device__ __align__(16) __nv_bfloat16 g_vlo[MROWS * HID];
__device__ __align__(16) __nv_bfloat16 g_xhi[MROWS * HID];
__device__ __align__(16) __nv_bfloat16 g_xlo[MROWS * HID];
__device__ __align__(16) __nv_bfloat16 g_whi[3 * HID * HID];
__device__ __align__(16) __nv_bfloat16 g_wlo[3 * HID * HID];

// ---------------------------------------------------------------------------
// mma.sync m16n8k16 bf16 (row.col), fp32 accumulate
// ---------------------------------------------------------------------------
__device__ __forceinline__ void mma16816(float* d, const uint32_t* a,
                                         const uint32_t* b) {
    asm volatile(
        "mma.sync.aligned.m16n8k16.row.col.f32.bf16.bf16.f32 "
        "{%0,%1,%2,%3}, {%4,%5,%6,%7}, {%8,%9}, {%0,%1,%2,%3};"
        : "+f"(d[0]), "+f"(d[1]), "+f"(d[2]), "+f"(d[3])
        : "r"(a[0]), "r"(a[1]), "r"(a[2]), "r"(a[3]),
          "r"(b[0]), "r"(b[1]));
}

__device__ __forceinline__ uint32_t bf2pack(float x, float y) {
    __nv_bfloat162 t = __float22bfloat162_rn(make_float2(x, y));
    return *(uint32_t*)&t;
}
__device__ __forceinline__ float bferr(float x) {
    return x - __bfloat162float(__float2bfloat16_rn(x));
}

// ---------------------------------------------------------------------------
// Split fp32 -> (hi, lo) bf16 pair.  which: 0=X, 1=Wq, 2=Wk, 3=Wv
// ---------------------------------------------------------------------------
__global__ void split_kernel(const float4* __restrict__ src, int which, int n4)
{
    __nv_bfloat16* hi;
    __nv_bfloat16* lo;
    if (which == 0) { hi = g_xhi; lo = g_xlo; }
    else { hi = g_whi + (size_t)(which - 1) * HID * HID;
           lo = g_wlo + (size_t)(which - 1) * HID * HID; }

    int i = blockIdx.x * blockDim.x + threadIdx.x;
    int stride = gridDim.x * blockDim.x;
    for (; i < n4; i += stride) {
        float4 v = src[i];
        uint2 hv, lv;
        hv.x = bf2pack(v.x, v.y);
        hv.y = bf2pack(v.z, v.w);
        lv.x = bf2pack(bferr(v.x), bferr(v.y));
        lv.y = bf2pack(bferr(v.z), bferr(v.w));
        ((uint2*)hi)[i] = hv;
        ((uint2*)lo)[i] = lv;
    }
}

// ---------------------------------------------------------------------------
// Split-bf16 GEMM via mma.sync: C = X @ W^T + b, output split to bf16 hi/lo.
// CTA tile 128x128, 8 warps (32M x 64N each), K-chunk 64.
// grid = (HID/128, MROWS/128, 3), block = 256.
// ---------------------------------------------------------------------------
#define TROW   72                      // halves per smem row (64 data + 8 pad)
#define TWORDS (128 * (TROW / 2))      // words per tile
#define GEMM_SMEM (4 * 128 * TROW * 2)

__global__ __launch_bounds__(256) void gemm_kernel(
    const float* __restrict__ b0,
    const float* __restrict__ b1,
    const float* __restrict__ b2)
{
    extern __shared__ __align__(16) __nv_bfloat16 sm[];
    __nv_bfloat16* tAhi = sm;
    __nv_bfloat16* tAlo = sm + 128 * TROW;
    __nv_bfloat16* tBhi = sm + 2 * 128 * TROW;
    __nv_bfloat16* tBlo = sm + 3 * 128 * TROW;
    const uint32_t* smw = (const uint32_t*)sm;

    const int tid  = threadIdx.x;
    const int wid  = tid >> 5;
    const int lane = tid & 31;
    const int g    = lane >> 2;
    const int cq   = lane & 3;

    const int n0 = blockIdx.x * 128;
    const int m0 = blockIdx.y * 128;
    const int z  = blockIdx.z;

    const __nv_bfloat16* Wh = g_whi + (size_t)z * HID * HID;
    const __nv_bfloat16* Wl = g_wlo + (size_t)z * HID * HID;
    const float* bias = (z == 0) ? b0 : (z == 1) ? b1 : b2;
    __nv_bfloat16* dhi = (z == 0) ? g_qhi : (z == 1) ? g_khi : g_vhi;
    __nv_bfloat16* dlo = (z == 0) ? g_qlo : (z == 1) ? g_klo : g_vlo;

    const int wm = (wid & 3) * 32;
    const int wn = (wid >> 2) * 64;

    float acc[2][8][4];
    #pragma unroll
    for (int mi = 0; mi < 2; mi++)
        #pragma unroll
        for (int nj = 0; nj < 8; nj++)
            #pragma unroll
            for (int r = 0; r < 4; r++) acc[mi][nj][r] = 0.f;

    const int lrow = tid >> 3;
    const int lcol = (tid & 7) * 8;

    for (int c = 0; c < HID / 64; c++) {
        const int k0 = c * 64;
        #pragma unroll
        for (int rr = 0; rr < 128; rr += 32) {
            const int row = rr + lrow;
            *(float4*)&tAhi[row * TROW + lcol] =
                *(const float4*)&g_xhi[(size_t)(m0 + row) * HID + k0 + lcol];
            *(float4*)&tAlo[row * TROW + lcol] =
                *(const float4*)&g_xlo[(size_t)(m0 + row) * HID + k0 + lcol];
            *(float4*)&tBhi[row * TROW + lcol] =
                *(const float4*)&Wh[(size_t)(n0 + row) * HID + k0 + lcol];
            *(float4*)&tBlo[row * TROW + lcol] =
                *(const float4*)&Wl[(size_t)(n0 + row) * HID + k0 + lcol];
        }
        __syncthreads();

        #pragma unroll
        for (int ks = 0; ks < 4; ks++) {
            uint32_t ah[2][4], al[2][4];
            #pragma unroll
            for (int mi = 0; mi < 2; mi++) {
                const int base = (wm + mi * 16 + g) * (TROW / 2) + ks * 8 + cq;
                ah[mi][0] = smw[base];
                ah[mi][1] = smw[base + 8 * (TROW / 2)];
                ah[mi][2] = smw[base + 4];
                ah[mi][3] = smw[base + 8 * (TROW / 2) + 4];
                al[mi][0] = smw[TWORDS + base];
                al[mi][1] = smw[TWORDS + base + 8 * (TROW / 2)];
                al[mi][2] = smw[TWORDS + base + 4];
                al[mi][3] = smw[TWORDS + base + 8 * (TROW / 2) + 4];
            }
            #pragma unroll
            for (int nj = 0; nj < 8; nj++) {
                const int bbase = (wn + nj * 8 + g) * (TROW / 2) + ks * 8 + cq;
                uint32_t bh[2], bl[2];
                bh[0] = smw[2 * TWORDS + bbase];
                bh[1] = smw[2 * TWORDS + bbase + 4];
                bl[0] = smw[3 * TWORDS + bbase];
                bl[1] = smw[3 * TWORDS + bbase + 4];
                #pragma unroll
                for (int mi = 0; mi < 2; mi++) {
                    mma16816(acc[mi][nj], ah[mi], bh);
                    mma16816(acc[mi][nj], ah[mi], bl);
                    mma16816(acc[mi][nj], al[mi], bh);
                }
            }
        }
        __syncthreads();
    }

    // Epilogue: add bias, split to bf16 hi/lo, store packed pairs
    #pragma unroll
    for (int mi = 0; mi < 2; mi++) {
        const int r0 = m0 + wm + mi * 16 + g;
        #pragma unroll
        for (int nj = 0; nj < 8; nj++) {
            const int col = n0 + wn + nj * 8 + cq * 2;
            const float bz0 = __ldg(&bias[col]);
            const float bz1 = __ldg(&bias[col + 1]);
            float v00 = acc[mi][nj][0] + bz0, v01 = acc[mi][nj][1] + bz1;
            float v10 = acc[mi][nj][2] + bz0, v11 = acc[mi][nj][3] + bz1;
            *(uint32_t*)&dhi[(size_t)r0 * HID + col] = bf2pack(v00, v01);
            *(uint32_t*)&dlo[(size_t)r0 * HID + col] = bf2pack(bferr(v00), bferr(v01));
            *(uint32_t*)&dhi[(size_t)(r0 + 8) * HID + col] = bf2pack(v10, v11);
            *(uint32_t*)&dlo[(size_t)(r0 + 8) * HID + col] = bf2pack(bferr(v10), bferr(v11));
        }
    }
}

// ---------------------------------------------------------------------------
// Tensor-core flash attention.
// grid = (SEQ/128, B*H), block = 256 (8 warps). Each warp: 16 query rows.
// Per 128-key iter: QK^T (split 3-product) -> online softmax in fragments ->
// P split hi/lo on the fly -> PV (split 3-product) against transposed V.
// ---------------------------------------------------------------------------
#define KROW 36                        // words per K-smem row (72 halves)
#define VROW 68                        // words per Vt-smem row (136 halves)
#define KHIW 0
#define KLOW (128 * KROW)              // 4608
#define VHIW (2 * 128 * KROW)          // 9216
#define VLOW (VHIW + 64 * VROW)        // 13568
#define ATTN_WORDS (VLOW + 64 * VROW)  // 17920
#define ATTN_SMEM (ATTN_WORDS * 4)     // 71680 B

__global__ __launch_bounds__(256) void attn_kernel(
    const float* __restrict__ mask, float* __restrict__ out)
{
    extern __shared__ __align__(16) uint32_t smw[];
    uint16_t* smh = (uint16_t*)smw;

    const int tid  = threadIdx.x;
    const int wid  = tid >> 5;
    const int lane = tid & 31;
    const int g    = lane >> 2;
    const int cq   = lane & 3;
    const int bh   = blockIdx.y;
    const int b    = bh >> 4;
    const int h    = bh & 15;
    const int q0   = blockIdx.x * 128;

    const int lrow = tid >> 3;
    const int lcol = (tid & 7) * 8;       // halves

    // ---- Stage Q tile (128 x 64, hi+lo) through K region, keep frags in regs
    #pragma unroll
    for (int rr = 0; rr < 128; rr += 32) {
        const int r = rr + lrow;
        const size_t off = ((size_t)(q0 + r) * BATCH + b) * HID + h * DH + lcol;
        *(uint4*)(smh + r * 72 + lcol)            = *(const uint4*)(g_qhi + off);
        *(uint4*)(smh + 2 * KLOW + r * 72 + lcol) = *(const uint4*)(g_qlo + off);
    }
    __syncthreads();

    uint32_t qh[4][4], ql[4][4];
    #pragma unroll
    for (int ks = 0; ks < 4; ks++) {
        const int base = (wid * 16 + g) * KROW + ks * 8 + cq;
        qh[ks][0] = smw[base];
        qh[ks][1] = smw[base + 8 * KROW];
        qh[ks][2] = smw[base + 4];
        qh[ks][3] = smw[base + 8 * KROW + 4];
        ql[ks][0] = smw[KLOW + base];
        ql[ks][1] = smw[KLOW + base + 8 * KROW];
        ql[ks][2] = smw[KLOW + base + 4];
        ql[ks][3] = smw[KLOW + base + 8 * KROW + 4];
    }

    float m0 = -1e30f, m1 = -1e30f, l0 = 0.f, l1 = 0.f;
    float oacc[8][4];
    #pragma unroll
    for (int j = 0; j < 8; j++)
        #pragma unroll
        for (int r = 0; r < 4; r++) oacc[j][r] = 0.f;

    const float scale = 0.125f;          // 1/sqrt(64)
    const int r0 = q0 + wid * 16 + g;    // this thread's query rows: r0, r0+8
    const float* mrow0 = mask + (size_t)b * SEQ * SEQ + (size_t)r0 * SEQ;
    const float* mrow1 = mrow0 + 8 * (size_t)SEQ;

    // V-transpose loader mapping
    const int vp = tid & 63;             // key pair index (keys 2vp, 2vp+1)
    const int vd0 = (tid >> 6) * 16;     // 16 d-values per thread

    for (int k0 = 0; k0 < SEQ; k0 += 128) {
        __syncthreads();
        // --- load K tile (128 keys x 64 d, hi+lo)
        #pragma unroll
        for (int rr = 0; rr < 128; rr += 32) {
            const int kk = rr + lrow;
            const size_t off = ((size_t)(k0 + kk) * BATCH + b) * HID + h * DH + lcol;
            *(uint4*)(smh + kk * 72 + lcol)            = *(const uint4*)(g_khi + off);
            *(uint4*)(smh + 2 * KLOW + kk * 72 + lcol) = *(const uint4*)(g_klo + off);
        }
        // --- load V tile transposed: Vt[d][key]
        {
            const size_t ra = ((size_t)(k0 + 2 * vp) * BATCH + b) * HID + h * DH + vd0;
            const size_t rb = ra + BATCH * HID;   // next key
            #pragma unroll
            for (int sp = 0; sp < 2; sp++) {
                const __nv_bfloat16* src = sp ? g_vlo : g_vhi;
                const int region = sp ? VLOW : VHIW;
                uint4 a0 = *(const uint4*)(src + ra);
                uint4 a1 = *(const uint4*)(src + ra + 8);
                uint4 c0 = *(const uint4*)(src + rb);
                uint4 c1 = *(const uint4*)(src + rb + 8);
                const uint32_t wa[8] = {a0.x, a0.y, a0.z, a0.w, a1.x, a1.y, a1.z, a1.w};
                const uint32_t wb[8] = {c0.x, c0.y, c0.z, c0.w, c1.x, c1.y, c1.z, c1.w};
                #pragma unroll
                for (int j = 0; j < 8; j++) {
                    smw[region + (vd0 + 2 * j)     * VROW + vp] = __byte_perm(wa[j], wb[j], 0x5410);
                    smw[region + (vd0 + 2 * j + 1) * VROW + vp] = __byte_perm(wa[j], wb[j], 0x7632);
                }
            }
        }
        __syncthreads();

        // --- S = Q K^T (16 n-tiles of 8 keys)
        float sa[16][4];
        #pragma unroll
        for (int nt = 0; nt < 16; nt++) {
            sa[nt][0] = 0.f; sa[nt][1] = 0.f; sa[nt][2] = 0.f; sa[nt][3] = 0.f;
            #pragma unroll
            for (int ks = 0; ks < 4; ks++) {
                const int ba = (nt * 8 + g) * KROW + ks * 8 + cq;
                uint32_t bhf[2], blf[2];
                bhf[0] = smw[ba];        bhf[1] = smw[ba + 4];
                blf[0] = smw[KLOW + ba]; blf[1] = smw[KLOW + ba + 4];
                mma16816(sa[nt], qh[ks], bhf);
                mma16816(sa[nt], qh[ks], blf);
                mma16816(sa[nt], ql[ks], bhf);
            }
        }

        // --- scale + mask + row max
        float nx0 = -1e30f, nx1 = -1e30f;
        #pragma unroll
        for (int nt = 0; nt < 16; nt++) {
            const float2 mv0 = *(const float2*)&mrow0[k0 + nt * 8 + 2 * cq];
            const float2 mv1 = *(const float2*)&mrow1[k0 + nt * 8 + 2 * cq];
            sa[nt][0] = fmaf(sa[nt][0], scale, mv0.x);
            sa[nt][1] = fmaf(sa[nt][1], scale, mv0.y);
            sa[nt][2] = fmaf(sa[nt][2], scale, mv1.x);
            sa[nt][3] = fmaf(sa[nt][3], scale, mv1.y);
            nx0 = fmaxf(nx0, fmaxf(sa[nt][0], sa[nt][1]));
            nx1 = fmaxf(nx1, fmaxf(sa[nt][2], sa[nt][3]));
        }
        nx0 = fmaxf(nx0, __shfl_xor_sync(0xffffffffu, nx0, 1));
        nx0 = fmaxf(nx0, __shfl_xor_sync(0xffffffffu, nx0, 2));
        nx1 = fmaxf(nx1, __shfl_xor_sync(0xffffffffu, nx1, 1));
        nx1 = fmaxf(nx1, __shfl_xor_sync(0xffffffffu, nx1, 2));

        const float mn0 = fmaxf(m0, nx0), mn1 = fmaxf(m1, nx1);
        const float c0s = __expf(m0 - mn0), c1s = __expf(m1 - mn1);
        m0 = mn0; m1 = mn1;
        l0 *= c0s; l1 *= c1s;
        #pragma unroll
        for (int j = 0; j < 8; j++) {
            oacc[j][0] *= c0s; oacc[j][1] *= c0s;
            oacc[j][2] *= c1s; oacc[j][3] *= c1s;
        }

        // --- P (split) and PV, per 16-key k-step
        #pragma unroll
        for (int kt = 0; kt < 8; kt++) {
            const float p00 = __expf(sa[2 * kt][0] - m0);
            const float p01 = __expf(sa[2 * kt][1] - m0);
            const float p10 = __expf(sa[2 * kt][2] - m1);
            const float p11 = __expf(sa[2 * kt][3] - m1);
            const float p20 = __expf(sa[2 * kt + 1][0] - m0);
            const float p21 = __expf(sa[2 * kt + 1][1] - m0);
            const float p30 = __expf(sa[2 * kt + 1][2] - m1);
            const float p31 = __expf(sa[2 * kt + 1][3] - m1);
            l0 += p00 + p01 + p20 + p21;
            l1 += p10 + p11 + p30 + p31;

            uint32_t pah[4], pal[4];
            pah[0] = bf2pack(p00, p01);
            pah[1] = bf2pack(p10, p11);
            pah[2] = bf2pack(p20, p21);
            pah[3] = bf2pack(p30, p31);
            pal[0] = bf2pack(bferr(p00), bferr(p01));
            pal[1] = bf2pack(bferr(p10), bferr(p11));
            pal[2] = bf2pack(bferr(p20), bferr(p21));
            pal[3] = bf2pack(bferr(p30), bferr(p31));

            #pragma unroll
            for (int nt2 = 0; nt2 < 8; nt2++) {
                const int ba = VHIW + (nt2 * 8 + g) * VROW + kt * 8 + cq;
                uint32_t vh2[2], vl2[2];
                vh2[0] = smw[ba];              vh2[1] = smw[ba + 4];
                vl2[0] = smw[ba + 64 * VROW];  vl2[1] = smw[ba + 64 * VROW + 4];
                mma16816(oacc[nt2], pah, vh2);
                mma16816(oacc[nt2], pah, vl2);
                mma16816(oacc[nt2], pal, vh2);
            }
        }
    }

    // --- reduce l over the 4 lanes sharing each row, normalize, store
    l0 += __shfl_xor_sync(0xffffffffu, l0, 1);
    l0 += __shfl_xor_sync(0xffffffffu, l0, 2);
    l1 += __shfl_xor_sync(0xffffffffu, l1, 1);
    l1 += __shfl_xor_sync(0xffffffffu, l1, 2);
    const float i0 = 1.0f / l0, i1 = 1.0f / l1;

    #pragma unroll
    for (int nt2 = 0; nt2 < 8; nt2++) {
        const int col = h * DH + nt2 * 8 + 2 * cq;
        const size_t o0 = (size_t)r0 * (BATCH * HID) + (size_t)b * HID + col;
        const size_t o1 = o0 + 8 * (size_t)(BATCH * HID);
        float2 v0, v1;
        v0.x = oacc[nt2][0] * i0; v0.y = oacc[nt2][1] * i0;
        v1.x = oacc[nt2][2] * i1; v1.y = oacc[nt2][3] * i1;
        *(float2*)&out[o0] = v0;
        *(float2*)&out[o1] = v1;
    }
}

// ---------------------------------------------------------------------------
// Launch
// ---------------------------------------------------------------------------
extern "C" void kernel_launch(void* const* d_in, const int* in_sizes, int n_in,
                              void* d_out, int out_size)
{
    const float* X    = (const float*)d_in[0];
    const float* mask = (const float*)d_in[1];
    const float* Wq   = (const float*)d_in[2];
    const float* bq   = (const float*)d_in[3];
    const float* Wk   = (const float*)d_in[4];
    const float* bk   = (const float*)d_in[5];
    const float* Wv   = (const float*)d_in[6];
    const float* bv   = (const float*)d_in[7];
    float* out = (float*)d_out;

    split_kernel<<<1024, 256>>>((const float4*)X, 0, MROWS * HID / 4);
    split_kernel<<<512, 256>>>((const float4*)Wq, 1, HID * HID / 4);
    split_kernel<<<512, 256>>>((const float4*)Wk, 2, HID * HID / 4);
    split_kernel<<<512, 256>>>((const float4*)Wv, 3, HID * HID / 4);

    cudaFuncSetAttribute(gemm_kernel,
                         cudaFuncAttributeMaxDynamicSharedMemorySize, GEMM_SMEM);
    dim3 ggrid(HID / 128, MROWS / 128, 3);
    gemm_kernel<<<ggrid, 256, GEMM_SMEM>>>(bq, bk, bv);

    cudaFuncSetAttribute(attn_kernel,
                         cudaFuncAttributeMaxDynamicSharedMemorySize, ATTN_SMEM);
    dim3 agrid(SEQ / 128, BHTOT);
    attn_kernel<<<agrid, 256, ATTN_SMEM>>>(mask, out);
}